// round 5
// baseline (speedup 1.0000x reference)
#include <cuda_runtime.h>

#define BB 32
#define TT 512
#define UU 512
#define NG 1536          // 3*U
#define OC 1024          // 2*U output channels

// x-gates scratch: [dir][B*T][3U] fp32 (192 MB, static device allocation)
__device__ float    g_xg[(size_t)2 * BB * TT * NG];
// per-step rh = r * h_prev exchange buffer
__device__ float    g_rh[2 * BB * UU];
// software grid barrier state (per direction)
__device__ unsigned g_cnt[2];
__device__ unsigned g_gen[2];

__device__ __forceinline__ float hsig(float v) {
    return fminf(fmaxf(0.2f * v + 0.5f, 0.0f), 1.0f);
}

// ---------------------------------------------------------------------------
// Phase 1: Xg[dir][m][n] = x[m][:] @ W_dir[:][n] + bias_dir[n]
// M = 16384, K = 512, N = 1536. BM=BN=64, BK=16, 256 thr, 4x4 reg tile.
// ---------------------------------------------------------------------------
__global__ void xgemm_kernel(const float* __restrict__ A,
                             const float* __restrict__ Wf, const float* __restrict__ bf,
                             const float* __restrict__ Wb, const float* __restrict__ bb)
{
    const int dir = blockIdx.z;
    const float* __restrict__ W    = dir ? Wb : Wf;
    const float* __restrict__ bias = dir ? bb : bf;
    const int m0 = blockIdx.y * 64;
    const int n0 = blockIdx.x * 64;

    __shared__ float As[16][64];   // [k][m]
    __shared__ float Bs[16][64];   // [k][n]

    const int tid = threadIdx.x;
    const int tx = tid & 15;       // -> n
    const int ty = tid >> 4;       // -> m

    float acc[4][4];
#pragma unroll
    for (int i = 0; i < 4; ++i)
#pragma unroll
        for (int j = 0; j < 4; ++j) acc[i][j] = 0.0f;

    const int arow = tid >> 2;           // 0..63
    const int akc  = (tid & 3) << 2;     // 0,4,8,12
    const int bkr  = tid >> 4;           // 0..15
    const int bnc  = (tid & 15) << 2;    // 0..60

    for (int k0 = 0; k0 < 512; k0 += 16) {
        float4 av = *(const float4*)(A + (size_t)(m0 + arow) * 512 + k0 + akc);
        As[akc + 0][arow] = av.x;
        As[akc + 1][arow] = av.y;
        As[akc + 2][arow] = av.z;
        As[akc + 3][arow] = av.w;
        *(float4*)&Bs[bkr][bnc] =
            *(const float4*)(W + (size_t)(k0 + bkr) * NG + n0 + bnc);
        __syncthreads();

#pragma unroll
        for (int kk = 0; kk < 16; ++kk) {
            float4 a4 = *(const float4*)&As[kk][ty << 2];
            float4 b4 = *(const float4*)&Bs[kk][tx << 2];
            float aa[4] = {a4.x, a4.y, a4.z, a4.w};
            float bv[4] = {b4.x, b4.y, b4.z, b4.w};
#pragma unroll
            for (int i = 0; i < 4; ++i)
#pragma unroll
                for (int j = 0; j < 4; ++j)
                    acc[i][j] = fmaf(aa[i], bv[j], acc[i][j]);
        }
        __syncthreads();
    }

    float* __restrict__ Cd = g_xg + (size_t)dir * BB * TT * NG;
    const int nbase = n0 + (tx << 2);
    float b0 = bias[nbase + 0], b1 = bias[nbase + 1],
          b2 = bias[nbase + 2], b3 = bias[nbase + 3];
#pragma unroll
    for (int i = 0; i < 4; ++i) {
        const int m = m0 + (ty << 2) + i;
        float4 o;
        o.x = acc[i][0] + b0;
        o.y = acc[i][1] + b1;
        o.z = acc[i][2] + b2;
        o.w = acc[i][3] + b3;
        *(float4*)&Cd[(size_t)m * NG + nbase] = o;
    }
}

// ---------------------------------------------------------------------------
// Software grid barrier: per-direction (64 blocks), monotonic generation.
// All 128 blocks are co-resident (1 block/SM, 128 <= 148 SMs) => no deadlock.
// ---------------------------------------------------------------------------
__device__ __forceinline__ void grid_bar(int dir, int tid, unsigned& bar_t)
{
    __syncthreads();
    if (tid == 0) {
        ++bar_t;                           // target generation
        __threadfence();                   // release this block's writes
        unsigned arrived = atomicAdd(&g_cnt[dir], 1u) + 1u;
        if (arrived == 64u) {
            atomicExch(&g_cnt[dir], 0u);
            __threadfence();
            atomicExch(&g_gen[dir], bar_t);
        } else {
            while ((int)(*(volatile unsigned*)&g_gen[dir] - bar_t) < 0) { }
            __threadfence();               // acquire
        }
    }
    __syncthreads();
}

// ---------------------------------------------------------------------------
// Phase 2: persistent scan. 128 blocks x 256 threads. Block = (dir, 8 cols).
// Per step: zr gates -> g_rh exchange -> barrier -> candidate -> out -> barrier.
// smem: sW 3*512*8 = 12288 | sH 32*513 = 16416 | red 2048  = 30752 floats
// ---------------------------------------------------------------------------
#define SCAN_SMEM_FLOATS (12288 + 16416 + 2048)
#define SCAN_SMEM_BYTES  (SCAN_SMEM_FLOATS * 4)

__global__ void __launch_bounds__(256, 1)
scan_kernel(const float* __restrict__ Uf,
            const float* __restrict__ Ub,
            float* __restrict__ out)
{
    extern __shared__ float sm[];
    float* sW  = sm;             // [g][u][c] : g*4096 + u*8 + c
    float* sH  = sm + 12288;     // [b][u]    : b*513 + u   (h_prev, then rh)
    float* red = sH + 16416;     // reduction scratch

    const int tid   = threadIdx.x;
    const int dir   = blockIdx.x >> 6;
    const int cg    = blockIdx.x & 63;
    const int hbase = cg << 3;
    const float* __restrict__ Urec = dir ? Ub : Uf;

    // --- weight slice, loaded ONCE: sW[g][u][c] = Urec[u][g*512 + hbase + c]
#pragma unroll 4
    for (int i = tid; i < 12288; i += 256) {
        const int c = i & 7;
        const int u = (i >> 3) & 511;
        const int g = i >> 12;
        sW[i] = Urec[(size_t)u * NG + g * UU + hbase + c];
    }

    unsigned bar_t = 0;
    if (tid == 0) bar_t = *(volatile unsigned*)&g_gen[dir];

    // GEMM-thread mapping
    const int ks = tid >> 6;            // 0..3 (K quarter)
    const int bg = (tid >> 3) & 7;      // 0..7 (batch group of 4)
    const int c  = tid & 7;             // 0..7 (column)
    const int u0 = ks << 7;
    // reduce-thread mapping
    const int rb = tid >> 3;            // 0..31 (batch)
    const int rc = tid & 7;             // 0..7  (column)
    const int j  = hbase + rc;

    const float* __restrict__ pw = sW + (u0 << 3) + c;
    const float* __restrict__ h0 = sH + (bg * 4 + 0) * 513 + u0;
    const float* __restrict__ h1 = h0 + 513;
    const float* __restrict__ h2 = h1 + 513;
    const float* __restrict__ h3 = h2 + 513;

    const size_t xg_base = (size_t)dir * BB * TT + (size_t)rb * TT;
    const int    rh_base = (dir * BB) << 9;

    float rz = 0.0f, rzh = 0.0f;        // z and z*h carried A -> B per thread

    for (int s = 0; s < TT; ++s) {
        // prefetch x-gate values (hidden under the FMA loops)
        const int t_x = dir ? (TT - 1 - s) : s;
        const float* __restrict__ xrow = g_xg + (xg_base + t_x) * NG;
        const float xz = xrow[j];
        const float xr = xrow[UU + j];
        const float xh = xrow[2 * UU + j];

        // ---- load h_prev into sH (L2 only: other blocks wrote it) ----
        if (s == 0) {
            for (int i = tid; i < 16416; i += 256) sH[i] = 0.0f;
        } else {
            const float* __restrict__ hp_base =
                out + (size_t)(s - 1) * OC + (size_t)dir * UU;
#pragma unroll 4
            for (int i = tid; i < 4096; i += 256) {
                const int b  = i >> 7;
                const int u4 = (i & 127) << 2;
                float4 v = __ldcg((const float4*)(hp_base + (size_t)b * TT * OC + u4));
                float* d = sH + b * 513 + u4;
                d[0] = v.x; d[1] = v.y; d[2] = v.z; d[3] = v.w;
            }
        }
        __syncthreads();

        // ---- phase A: z/r gate GEMM ----
        float az0 = 0.f, az1 = 0.f, az2 = 0.f, az3 = 0.f;
        float ar0 = 0.f, ar1 = 0.f, ar2 = 0.f, ar3 = 0.f;
#pragma unroll 8
        for (int uu = 0; uu < 128; ++uu) {
            const float wz = pw[uu * 8];
            const float wr = pw[uu * 8 + 4096];
            const float v0 = h0[uu];
            const float v1 = h1[uu];
            const float v2 = h2[uu];
            const float v3 = h3[uu];
            az0 = fmaf(v0, wz, az0); ar0 = fmaf(v0, wr, ar0);
            az1 = fmaf(v1, wz, az1); ar1 = fmaf(v1, wr, ar1);
            az2 = fmaf(v2, wz, az2); ar2 = fmaf(v2, wr, ar2);
            az3 = fmaf(v3, wz, az3); ar3 = fmaf(v3, wr, ar3);
        }
        {
            float* rp = red + ks * 512 + (bg * 4) * 16 + c;
            rp[0]  = az0; rp[8]  = ar0;
            rp[16] = az1; rp[24] = ar1;
            rp[32] = az2; rp[40] = ar2;
            rp[48] = az3; rp[56] = ar3;
        }
        __syncthreads();
        {
            const float* rr = red + rb * 16 + rc;
            const float hz = rr[0] + rr[512] + rr[1024] + rr[1536];
            const float hr = rr[8] + rr[520] + rr[1032] + rr[1544];
            const float z  = hsig(xz + hz);
            const float r  = hsig(xr + hr);
            const float hp = sH[rb * 513 + j];
            rz  = z;
            rzh = z * hp;
            g_rh[rh_base + (rb << 9) + j] = r * hp;
        }
        grid_bar(dir, tid, bar_t);

        // ---- load rh into sH (overwrite; L2 only) ----
#pragma unroll 4
        for (int i = tid; i < 4096; i += 256) {
            const int b  = i >> 7;
            const int u4 = (i & 127) << 2;
            float4 v = __ldcg((const float4*)(g_rh + rh_base + (b << 9) + u4));
            float* d = sH + b * 513 + u4;
            d[0] = v.x; d[1] = v.y; d[2] = v.z; d[3] = v.w;
        }
        __syncthreads();

        // ---- phase B: candidate GEMM (Uh at sW offset 8192) ----
        float ah0 = 0.f, ah1 = 0.f, ah2 = 0.f, ah3 = 0.f;
#pragma unroll 8
        for (int uu = 0; uu < 128; ++uu) {
            const float wh = pw[uu * 8 + 8192];
            ah0 = fmaf(h0[uu], wh, ah0);
            ah1 = fmaf(h1[uu], wh, ah1);
            ah2 = fmaf(h2[uu], wh, ah2);
            ah3 = fmaf(h3[uu], wh, ah3);
        }
        {
            float* rp = red + ks * 256 + (bg * 4) * 8 + c;
            rp[0]  = ah0;
            rp[8]  = ah1;
            rp[16] = ah2;
            rp[24] = ah3;
        }
        __syncthreads();
        {
            const float* rr = red + rb * 8 + rc;
            const float hh   = rr[0] + rr[256] + rr[512] + rr[768];
            const float cand = tanhf(xh + hh);
            const float hnew = rzh + (1.0f - rz) * cand;
            out[((size_t)rb * TT + s) * OC + (size_t)dir * UU + j] = hnew;
        }
        grid_bar(dir, tid, bar_t);
    }
}

// ---------------------------------------------------------------------------
extern "C" void kernel_launch(void* const* d_in, const int* in_sizes, int n_in,
                              void* d_out, int out_size)
{
    (void)in_sizes; (void)n_in; (void)out_size;
    const float* x  = (const float*)d_in[0];
    const float* Wf = (const float*)d_in[1];
    const float* Uf = (const float*)d_in[2];
    const float* bf = (const float*)d_in[3];
    const float* Wb = (const float*)d_in[4];
    const float* Ub = (const float*)d_in[5];
    const float* bb = (const float*)d_in[6];
    float* out = (float*)d_out;

    cudaFuncSetAttribute(scan_kernel,
                         cudaFuncAttributeMaxDynamicSharedMemorySize,
                         SCAN_SMEM_BYTES);

    dim3 g1(NG / 64, (BB * TT) / 64, 2);   // 24 x 256 x 2
    xgemm_kernel<<<g1, 256>>>(x, Wf, bf, Wb, bb);

    scan_kernel<<<128, 256, SCAN_SMEM_BYTES>>>(Uf, Ub, out);
}

// round 6
// speedup vs baseline: 1.0033x; 1.0033x over previous
#include <cuda_runtime.h>

#define BB 32
#define TT 512
#define UU 512
#define NG 1536          // 3*U
#define OC 1024          // 2*U output channels

// x-gates scratch: [dir][B*T][3U] fp32 (192 MB, static device allocation)
__device__ float    g_xg[(size_t)2 * BB * TT * NG];
// per-step rh = r * h_prev exchange buffer
__device__ float    g_rh[2 * BB * UU];
// software grid barrier state (per direction)
__device__ unsigned g_cnt[2];
__device__ unsigned g_gen[2];

__device__ __forceinline__ float hsig(float v) {
    return fminf(fmaxf(0.2f * v + 0.5f, 0.0f), 1.0f);
}

// ---------------------------------------------------------------------------
// Phase 1: Xg[dir][m][n] = x[m][:] @ W_dir[:][n] + bias_dir[n]
// M = 16384, K = 512, N = 1536. BM=BN=64, BK=16, 256 thr, 4x4 reg tile.
// ---------------------------------------------------------------------------
__global__ void xgemm_kernel(const float* __restrict__ A,
                             const float* __restrict__ Wf, const float* __restrict__ bf,
                             const float* __restrict__ Wb, const float* __restrict__ bb)
{
    const int dir = blockIdx.z;
    const float* __restrict__ W    = dir ? Wb : Wf;
    const float* __restrict__ bias = dir ? bb : bf;
    const int m0 = blockIdx.y * 64;
    const int n0 = blockIdx.x * 64;

    __shared__ float As[16][64];   // [k][m]
    __shared__ float Bs[16][64];   // [k][n]

    const int tid = threadIdx.x;
    const int tx = tid & 15;       // -> n
    const int ty = tid >> 4;       // -> m

    float acc[4][4];
#pragma unroll
    for (int i = 0; i < 4; ++i)
#pragma unroll
        for (int j = 0; j < 4; ++j) acc[i][j] = 0.0f;

    const int arow = tid >> 2;           // 0..63
    const int akc  = (tid & 3) << 2;     // 0,4,8,12
    const int bkr  = tid >> 4;           // 0..15
    const int bnc  = (tid & 15) << 2;    // 0..60

    for (int k0 = 0; k0 < 512; k0 += 16) {
        float4 av = *(const float4*)(A + (size_t)(m0 + arow) * 512 + k0 + akc);
        As[akc + 0][arow] = av.x;
        As[akc + 1][arow] = av.y;
        As[akc + 2][arow] = av.z;
        As[akc + 3][arow] = av.w;
        *(float4*)&Bs[bkr][bnc] =
            *(const float4*)(W + (size_t)(k0 + bkr) * NG + n0 + bnc);
        __syncthreads();

#pragma unroll
        for (int kk = 0; kk < 16; ++kk) {
            float4 a4 = *(const float4*)&As[kk][ty << 2];
            float4 b4 = *(const float4*)&Bs[kk][tx << 2];
            float aa[4] = {a4.x, a4.y, a4.z, a4.w};
            float bv[4] = {b4.x, b4.y, b4.z, b4.w};
#pragma unroll
            for (int i = 0; i < 4; ++i)
#pragma unroll
                for (int j = 0; j < 4; ++j)
                    acc[i][j] = fmaf(aa[i], bv[j], acc[i][j]);
        }
        __syncthreads();
    }

    float* __restrict__ Cd = g_xg + (size_t)dir * BB * TT * NG;
    const int nbase = n0 + (tx << 2);
    float b0 = bias[nbase + 0], b1 = bias[nbase + 1],
          b2 = bias[nbase + 2], b3 = bias[nbase + 3];
#pragma unroll
    for (int i = 0; i < 4; ++i) {
        const int m = m0 + (ty << 2) + i;
        float4 o;
        o.x = acc[i][0] + b0;
        o.y = acc[i][1] + b1;
        o.z = acc[i][2] + b2;
        o.w = acc[i][3] + b3;
        *(float4*)&Cd[(size_t)m * NG + nbase] = o;
    }
}

// ---------------------------------------------------------------------------
// Software grid barrier: per-direction (64 blocks), monotonic generation.
// All 128 blocks are co-resident (1 block/SM, 128 <= 148 SMs) => no deadlock.
// ---------------------------------------------------------------------------
__device__ __forceinline__ void grid_bar(int dir, int tid, unsigned& bar_t)
{
    __syncthreads();
    if (tid == 0) {
        ++bar_t;                           // target generation
        __threadfence();                   // release this block's writes
        unsigned arrived = atomicAdd(&g_cnt[dir], 1u) + 1u;
        if (arrived == 64u) {
            atomicExch(&g_cnt[dir], 0u);
            __threadfence();
            atomicExch(&g_gen[dir], bar_t);
        } else {
            while ((int)(*(volatile unsigned*)&g_gen[dir] - bar_t) < 0) { }
            __threadfence();               // acquire
        }
    }
    __syncthreads();
}

// ---------------------------------------------------------------------------
// Phase 2: persistent scan. 128 blocks x 256 threads. Block = (dir, 8 cols).
// Per step: zr gates -> g_rh exchange -> barrier -> candidate -> out -> barrier.
// smem: sW 3*512*8 = 12288 | sH 32*513 = 16416 | red 2048  = 30752 floats
// ---------------------------------------------------------------------------
#define SCAN_SMEM_FLOATS (12288 + 16416 + 2048)
#define SCAN_SMEM_BYTES  (SCAN_SMEM_FLOATS * 4)

__global__ void __launch_bounds__(256, 1)
scan_kernel(const float* __restrict__ Uf,
            const float* __restrict__ Ub,
            float* __restrict__ out)
{
    extern __shared__ float sm[];
    float* sW  = sm;             // [g][u][c] : g*4096 + u*8 + c
    float* sH  = sm + 12288;     // [b][u]    : b*513 + u   (h_prev, then rh)
    float* red = sH + 16416;     // reduction scratch

    const int tid   = threadIdx.x;
    const int dir   = blockIdx.x >> 6;
    const int cg    = blockIdx.x & 63;
    const int hbase = cg << 3;
    const float* __restrict__ Urec = dir ? Ub : Uf;

    // --- weight slice, loaded ONCE: sW[g][u][c] = Urec[u][g*512 + hbase + c]
#pragma unroll 4
    for (int i = tid; i < 12288; i += 256) {
        const int c = i & 7;
        const int u = (i >> 3) & 511;
        const int g = i >> 12;
        sW[i] = Urec[(size_t)u * NG + g * UU + hbase + c];
    }

    unsigned bar_t = 0;
    if (tid == 0) bar_t = *(volatile unsigned*)&g_gen[dir];

    // GEMM-thread mapping
    const int ks = tid >> 6;            // 0..3 (K quarter)
    const int bg = (tid >> 3) & 7;      // 0..7 (batch group of 4)
    const int c  = tid & 7;             // 0..7 (column)
    const int u0 = ks << 7;
    // reduce-thread mapping
    const int rb = tid >> 3;            // 0..31 (batch)
    const int rc = tid & 7;             // 0..7  (column)
    const int j  = hbase + rc;

    const float* __restrict__ pw = sW + (u0 << 3) + c;
    const float* __restrict__ h0 = sH + (bg * 4 + 0) * 513 + u0;
    const float* __restrict__ h1 = h0 + 513;
    const float* __restrict__ h2 = h1 + 513;
    const float* __restrict__ h3 = h2 + 513;

    const size_t xg_base = (size_t)dir * BB * TT + (size_t)rb * TT;
    const int    rh_base = (dir * BB) << 9;

    float rz = 0.0f, rzh = 0.0f;        // z and z*h carried A -> B per thread

    for (int s = 0; s < TT; ++s) {
        // prefetch x-gate values (hidden under the FMA loops)
        const int t_x = dir ? (TT - 1 - s) : s;
        const float* __restrict__ xrow = g_xg + (xg_base + t_x) * NG;
        const float xz = xrow[j];
        const float xr = xrow[UU + j];
        const float xh = xrow[2 * UU + j];

        // ---- load h_prev into sH (L2 only: other blocks wrote it) ----
        if (s == 0) {
            for (int i = tid; i < 16416; i += 256) sH[i] = 0.0f;
        } else {
            const float* __restrict__ hp_base =
                out + (size_t)(s - 1) * OC + (size_t)dir * UU;
#pragma unroll 4
            for (int i = tid; i < 4096; i += 256) {
                const int b  = i >> 7;
                const int u4 = (i & 127) << 2;
                float4 v = __ldcg((const float4*)(hp_base + (size_t)b * TT * OC + u4));
                float* d = sH + b * 513 + u4;
                d[0] = v.x; d[1] = v.y; d[2] = v.z; d[3] = v.w;
            }
        }
        __syncthreads();

        // ---- phase A: z/r gate GEMM ----
        float az0 = 0.f, az1 = 0.f, az2 = 0.f, az3 = 0.f;
        float ar0 = 0.f, ar1 = 0.f, ar2 = 0.f, ar3 = 0.f;
#pragma unroll 8
        for (int uu = 0; uu < 128; ++uu) {
            const float wz = pw[uu * 8];
            const float wr = pw[uu * 8 + 4096];
            const float v0 = h0[uu];
            const float v1 = h1[uu];
            const float v2 = h2[uu];
            const float v3 = h3[uu];
            az0 = fmaf(v0, wz, az0); ar0 = fmaf(v0, wr, ar0);
            az1 = fmaf(v1, wz, az1); ar1 = fmaf(v1, wr, ar1);
            az2 = fmaf(v2, wz, az2); ar2 = fmaf(v2, wr, ar2);
            az3 = fmaf(v3, wz, az3); ar3 = fmaf(v3, wr, ar3);
        }
        {
            float* rp = red + ks * 512 + (bg * 4) * 16 + c;
            rp[0]  = az0; rp[8]  = ar0;
            rp[16] = az1; rp[24] = ar1;
            rp[32] = az2; rp[40] = ar2;
            rp[48] = az3; rp[56] = ar3;
        }
        __syncthreads();
        {
            const float* rr = red + rb * 16 + rc;
            const float hz = rr[0] + rr[512] + rr[1024] + rr[1536];
            const float hr = rr[8] + rr[520] + rr[1032] + rr[1544];
            const float z  = hsig(xz + hz);
            const float r  = hsig(xr + hr);
            const float hp = sH[rb * 513 + j];
            rz  = z;
            rzh = z * hp;
            g_rh[rh_base + (rb << 9) + j] = r * hp;
        }
        grid_bar(dir, tid, bar_t);

        // ---- load rh into sH (overwrite; L2 only) ----
#pragma unroll 4
        for (int i = tid; i < 4096; i += 256) {
            const int b  = i >> 7;
            const int u4 = (i & 127) << 2;
            float4 v = __ldcg((const float4*)(g_rh + rh_base + (b << 9) + u4));
            float* d = sH + b * 513 + u4;
            d[0] = v.x; d[1] = v.y; d[2] = v.z; d[3] = v.w;
        }
        __syncthreads();

        // ---- phase B: candidate GEMM (Uh at sW offset 8192) ----
        float ah0 = 0.f, ah1 = 0.f, ah2 = 0.f, ah3 = 0.f;
#pragma unroll 8
        for (int uu = 0; uu < 128; ++uu) {
            const float wh = pw[uu * 8 + 8192];
            ah0 = fmaf(h0[uu], wh, ah0);
            ah1 = fmaf(h1[uu], wh, ah1);
            ah2 = fmaf(h2[uu], wh, ah2);
            ah3 = fmaf(h3[uu], wh, ah3);
        }
        {
            float* rp = red + ks * 256 + (bg * 4) * 8 + c;
            rp[0]  = ah0;
            rp[8]  = ah1;
            rp[16] = ah2;
            rp[24] = ah3;
        }
        __syncthreads();
        {
            const float* rr = red + rb * 8 + rc;
            const float hh   = rr[0] + rr[256] + rr[512] + rr[768];
            const float cand = tanhf(xh + hh);
            const float hnew = rzh + (1.0f - rz) * cand;
            out[((size_t)rb * TT + s) * OC + (size_t)dir * UU + j] = hnew;
        }
        grid_bar(dir, tid, bar_t);
    }
}

// ---------------------------------------------------------------------------
extern "C" void kernel_launch(void* const* d_in, const int* in_sizes, int n_in,
                              void* d_out, int out_size)
{
    (void)in_sizes; (void)n_in; (void)out_size;
    const float* x  = (const float*)d_in[0];
    const float* Wf = (const float*)d_in[1];
    const float* Uf = (const float*)d_in[2];
    const float* bf = (const float*)d_in[3];
    const float* Wb = (const float*)d_in[4];
    const float* Ub = (const float*)d_in[5];
    const float* bb = (const float*)d_in[6];
    float* out = (float*)d_out;

    cudaFuncSetAttribute(scan_kernel,
                         cudaFuncAttributeMaxDynamicSharedMemorySize,
                         SCAN_SMEM_BYTES);

    dim3 g1(NG / 64, (BB * TT) / 64, 2);   // 24 x 256 x 2
    xgemm_kernel<<<g1, 256>>>(x, Wf, bf, Wb, bb);

    scan_kernel<<<128, 256, SCAN_SMEM_BYTES>>>(Uf, Ub, out);
}